// round 7
// baseline (speedup 1.0000x reference)
#include <cuda_runtime.h>
#include <cstdint>

#define GRID_N   64
#define GRID_N3  (64 * 64 * 64)      // 262144
#define BMAX     8
#define NCELLS   (BMAX * GRID_N3)    // 2097152
#define NBINS    (BMAX * GRID_N * GRID_N)   // 32768 column bins (b, x, y)
#define LMAX     (1 << 20)           // >= 1,000,000 particles
#define EPS_CLIP 1e-5f
#define EPS_DIV  1e-7f

// Scratch grid: interleaved {weight, weight*prob} per cell + guard pads for
// the uniform 4-cell RED windows (zero-weight spills are numerical no-ops).
#define PAD 2
__device__ __align__(16) float2  g_grid_raw[PAD + NCELLS + PAD];
__device__ unsigned              g_hist[NBINS];
__device__ unsigned              g_cursor[NBINS];
__device__ __align__(16) float4  g_sval[LMAX];   // sorted {fx, fy, fz, prob}
__device__ unsigned              g_skey[LMAX];   // sorted packed (b,bx,by,bz)

__device__ __forceinline__ void red_add_v4(float2* addr, float a, float b, float c, float d) {
    asm volatile("red.global.add.v4.f32 [%0], {%1, %2, %3, %4};"
                 :: "l"(addr), "f"(a), "f"(b), "f"(c), "f"(d) : "memory");
}

__device__ __forceinline__ float clipf(float v) {
    return fminf(fmaxf(v, EPS_CLIP), 1.0f - EPS_CLIP);
}

// ---------------------------------------------------------------------------
// Pass 1: zero grid scratch + histogram
// ---------------------------------------------------------------------------
__global__ void __launch_bounds__(256) zero_kernel(int n4) {
    int stride = gridDim.x * blockDim.x;
    int tid = blockIdx.x * blockDim.x + threadIdx.x;
    float4* g = reinterpret_cast<float4*>(g_grid_raw);
    const float4 z = make_float4(0.f, 0.f, 0.f, 0.f);
    for (int i = tid; i < n4; i += stride) g[i] = z;
    for (int i = tid; i < NBINS; i += stride) g_hist[i] = 0u;
}

// ---------------------------------------------------------------------------
// Pass 2: histogram over (b, bx, by) column bins
// ---------------------------------------------------------------------------
__global__ void __launch_bounds__(256) hist_kernel(
    const float* __restrict__ pos, const int* __restrict__ bidx, int L)
{
    int i = blockIdx.x * blockDim.x + threadIdx.x;
    if (i >= L) return;
    int bx = (int)(clipf(__ldg(&pos[3 * i + 0])) * 64.0f);
    int by = (int)(clipf(__ldg(&pos[3 * i + 1])) * 64.0f);
    int b  = __ldg(&bidx[i]) & 7;
    atomicAdd(&g_hist[(b << 12) | (bx << 6) | by], 1u);
}

// ---------------------------------------------------------------------------
// Pass 3: exclusive scan of 32K bins -> g_cursor. One block, 1024 threads,
// 32 bins per thread (serial) + Hillis-Steele block scan.
// ---------------------------------------------------------------------------
__global__ void __launch_bounds__(1024) scan_kernel() {
    __shared__ unsigned s[1024];
    int tid = threadIdx.x;
    int base = tid * 32;

    unsigned loc[32];
    unsigned sum = 0;
    #pragma unroll
    for (int k = 0; k < 32; k++) {
        unsigned v = g_hist[base + k];
        loc[k] = sum;            // exclusive within chunk
        sum += v;
    }
    s[tid] = sum;
    __syncthreads();
    for (int d = 1; d < 1024; d <<= 1) {
        unsigned v = (tid >= d) ? s[tid - d] : 0u;
        __syncthreads();
        s[tid] += v;
        __syncthreads();
    }
    unsigned off = (tid == 0) ? 0u : s[tid - 1];
    #pragma unroll
    for (int k = 0; k < 32; k++)
        g_cursor[base + k] = off + loc[k];
}

// ---------------------------------------------------------------------------
// Pass 4: reorder particles into column-sorted order
// ---------------------------------------------------------------------------
__global__ void __launch_bounds__(256) reorder_kernel(
    const float* __restrict__ pos, const float* __restrict__ prob,
    const int* __restrict__ bidx, int L)
{
    int i = blockIdx.x * blockDim.x + threadIdx.x;
    if (i >= L) return;

    float xp = clipf(__ldg(&pos[3 * i + 0])) * 64.0f;
    float yp = clipf(__ldg(&pos[3 * i + 1])) * 64.0f;
    float zp = clipf(__ldg(&pos[3 * i + 2])) * 64.0f;
    int bx = (int)xp, by = (int)yp, bz = (int)zp;
    float fx = xp - (float)bx, fy = yp - (float)by, fz = zp - (float)bz;
    int b = __ldg(&bidx[i]) & 7;

    unsigned bin = (unsigned)((b << 12) | (bx << 6) | by);
    unsigned slot = atomicAdd(&g_cursor[bin], 1u);
    g_sval[slot] = make_float4(fx, fy, fz, __ldg(&prob[i]));
    g_skey[slot] = (unsigned)((b << 18) | (bx << 12) | (by << 6) | bz);
}

// ---------------------------------------------------------------------------
// Pass 5: scatter from sorted order. Warp lanes share a grid column ->
// coalesced RED wavefronts. Branchless 2x red.v4 per (x,y) tap.
// ---------------------------------------------------------------------------
__global__ void __launch_bounds__(256) scatter_kernel(int L) {
    int i = blockIdx.x * blockDim.x + threadIdx.x;
    if (i >= L) return;

    unsigned key = g_skey[i];
    float4 v = g_sval[i];
    int b  = (key >> 18) & 7;
    int bx = (key >> 12) & 63;
    int by = (key >> 6) & 63;
    int bz = key & 63;
    float fx = v.x, fy = v.y, fz = v.z, pr = v.w;

    float wx0 = 0.5f * (1.0f - fx) * (1.0f - fx);
    float wx1 = 0.75f - (fx - 0.5f) * (fx - 0.5f);
    float wx2 = 0.5f * fx * fx;
    float wy0 = 0.5f * (1.0f - fy) * (1.0f - fy);
    float wy1 = 0.75f - (fy - 0.5f) * (fy - 0.5f);
    float wy2 = 0.5f * fy * fy;
    float wz0 = 0.5f * (1.0f - fz) * (1.0f - fz);
    float wz1 = 0.75f - (fz - 0.5f) * (fz - 0.5f);
    float wz2 = 0.5f * fz * fz;

    if (bz < 1)  wz0 = 0.0f;
    if (bz > 62) wz2 = 0.0f;
    float wxa0 = (bx >= 1)  ? wx0 : 0.0f;
    float wxa2 = (bx <= 62) ? wx2 : 0.0f;
    float wya0 = (by >= 1)  ? wy0 : 0.0f;
    float wya2 = (by <= 62) ? wy2 : 0.0f;

    int  z0   = (bz - 1) & ~1;                 // may be -2 (guard pad)
    bool oddz = (bz & 1) != 0;
    float c0 = oddz ? wz0 : 0.0f;
    float c1 = oddz ? wz1 : wz0;
    float c2 = oddz ? wz2 : wz1;
    float c3 = oddz ? 0.0f : wz2;
    float d0 = c0 * pr, d1 = c1 * pr, d2 = c2 * pr, d3 = c3 * pr;

    int tx0 = max(bx - 1, 0) << 12;
    int tx1 = bx << 12;
    int tx2 = min(bx + 1, 63) << 12;
    int ty0 = max(by - 1, 0) << 6;
    int ty1 = by << 6;
    int ty2 = min(by + 1, 63) << 6;

    float2* gbase = g_grid_raw + PAD + (unsigned)b * GRID_N3 + z0;

    int   xo[3]  = {tx0, tx1, tx2};
    float wxv[3] = {wxa0, wx1, wxa2};
    int   yo[3]  = {ty0, ty1, ty2};
    float wyv[3] = {wya0, wy1, wya2};

    #pragma unroll
    for (int ox = 0; ox < 3; ox++) {
        #pragma unroll
        for (int oy = 0; oy < 3; oy++) {
            float wxy = wxv[ox] * wyv[oy];
            float2* p = gbase + (xo[ox] + yo[oy]);
            red_add_v4(p,     wxy * c0, wxy * d0, wxy * c1, wxy * d1);
            red_add_v4(p + 2, wxy * c2, wxy * d2, wxy * c3, wxy * d3);
        }
    }
}

// ---------------------------------------------------------------------------
// Pass 6: out = wp / (w + eps). 4 cells per thread.
// ---------------------------------------------------------------------------
__global__ void __launch_bounds__(256) divide_kernel(float* __restrict__ out, int n4) {
    int i = blockIdx.x * blockDim.x + threadIdx.x;
    if (i >= n4) return;
    const float4* g = reinterpret_cast<const float4*>(g_grid_raw + PAD);
    float4 a = g[2 * i];
    float4 b = g[2 * i + 1];
    float4 r;
    r.x = a.y / (a.x + EPS_DIV);
    r.y = a.w / (a.z + EPS_DIV);
    r.z = b.y / (b.x + EPS_DIV);
    r.w = b.w / (b.z + EPS_DIV);
    reinterpret_cast<float4*>(out)[i] = r;
}

// ---------------------------------------------------------------------------
extern "C" void kernel_launch(void* const* d_in, const int* in_sizes, int n_in,
                              void* d_out, int out_size)
{
    const float* pos  = (const float*)d_in[0];
    const float* prob = (const float*)d_in[1];
    const int*   bidx = (const int*)d_in[2];
    int L = in_sizes[1];                         // particle count

    int n4_zero = (int)(sizeof(g_grid_raw) / sizeof(float4));
    int pblocks = (L + 255) / 256;

    zero_kernel<<<2048, 256>>>(n4_zero);
    hist_kernel<<<pblocks, 256>>>(pos, bidx, L);
    scan_kernel<<<1, 1024>>>();
    reorder_kernel<<<pblocks, 256>>>(pos, prob, bidx, L);
    scatter_kernel<<<pblocks, 256>>>(L);

    int n4_div = out_size / 4;
    divide_kernel<<<(n4_div + 255) / 256, 256>>>((float*)d_out, n4_div);
}

// round 10
// speedup vs baseline: 1.0431x; 1.0431x over previous
#include <cuda_runtime.h>
#include <cstdint>

#define GRID_N   64
#define GRID_N3  (64 * 64 * 64)        // 262144
#define BMAX     8
#define NBINS    (BMAX * GRID_N * GRID_N)   // 32768 column bins (b,x,y)
#define LMAX     (1 << 20)
#define EPS_CLIP 1e-5f
#define EPS_DIV  1e-7f

// column accumulator: 66 z-slots (zi = bz+t in [0,65]; zi 0 and 65 are the
// dropped out-of-box taps) x 2 values = 132 floats; stride 139 (odd) makes
// the 32 lane-private copies bank-conflict-free.
#define ACC_STRIDE 139
#define ACC_USED   132

__device__ __align__(16) float4  g_sval[LMAX];     // sorted {xg, yg, zg, prob}
__device__ unsigned              g_hist[NBINS];
__device__ unsigned              g_cursor[NBINS];
__device__ unsigned              g_start[NBINS + 1];
__device__ unsigned              g_bsum[128];
__device__ unsigned              g_boff[128];

__device__ __forceinline__ float clipf(float v) {
    return fminf(fmaxf(v, EPS_CLIP), 1.0f - EPS_CLIP);
}

// weight of a particle (frac f) on the neighbor-offset-d column (d = bin - target)
__device__ __forceinline__ float wsel(int d, float f) {
    if (d < 0)  return 0.5f * f * f;                         // tap +1
    if (d > 0)  { float t = 1.0f - f; return 0.5f * t * t; } // tap -1
    float t = f - 0.5f; return 0.75f - t * t;                // tap 0
}

// ---------------------------------------------------------------------------
// zero histogram
// ---------------------------------------------------------------------------
__global__ void zero_hist_kernel() {
    int i = blockIdx.x * blockDim.x + threadIdx.x;
    if (i < NBINS) g_hist[i] = 0u;
}

// ---------------------------------------------------------------------------
// histogram over (b,x,y) column bins
// ---------------------------------------------------------------------------
__global__ void __launch_bounds__(256) hist_kernel(
    const float* __restrict__ pos, const int* __restrict__ bidx, int L)
{
    int i = blockIdx.x * blockDim.x + threadIdx.x;
    if (i >= L) return;
    int bx = (int)(clipf(__ldg(&pos[3 * i + 0])) * 64.0f);
    int by = (int)(clipf(__ldg(&pos[3 * i + 1])) * 64.0f);
    int b  = __ldg(&bidx[i]) & 7;
    atomicAdd(&g_hist[(b << 12) | (bx << 6) | by], 1u);
}

// ---------------------------------------------------------------------------
// 3-kernel coalesced exclusive scan of 32K bins
// ---------------------------------------------------------------------------
__global__ void __launch_bounds__(256) scan1_kernel() {   // 128 blocks x 256
    __shared__ unsigned s[256];
    int t = threadIdx.x;
    int gid = blockIdx.x * 256 + t;
    unsigned v = g_hist[gid];
    s[t] = v;
    __syncthreads();
    // inclusive Hillis-Steele
    for (int d = 1; d < 256; d <<= 1) {
        unsigned u = (t >= d) ? s[t - d] : 0u;
        __syncthreads();
        s[t] += u;
        __syncthreads();
    }
    g_cursor[gid] = s[t] - v;                 // exclusive within block
    if (t == 255) g_bsum[blockIdx.x] = s[t];  // block total
}

__global__ void __launch_bounds__(128) scan2_kernel() {   // 1 block x 128
    __shared__ unsigned s[128];
    int t = threadIdx.x;
    unsigned v = g_bsum[t];
    s[t] = v;
    __syncthreads();
    for (int d = 1; d < 128; d <<= 1) {
        unsigned u = (t >= d) ? s[t - d] : 0u;
        __syncthreads();
        s[t] += u;
        __syncthreads();
    }
    g_boff[t] = s[t] - v;
    if (t == 127) g_start[NBINS] = s[t];      // total = L
}

__global__ void __launch_bounds__(256) scan3_kernel() {   // 128 blocks x 256
    int gid = blockIdx.x * 256 + threadIdx.x;
    unsigned v = g_cursor[gid] + g_boff[blockIdx.x];
    g_cursor[gid] = v;
    g_start[gid]  = v;
}

// ---------------------------------------------------------------------------
// reorder particles into column-bin-sorted order
// ---------------------------------------------------------------------------
__global__ void __launch_bounds__(256) reorder_kernel(
    const float* __restrict__ pos, const float* __restrict__ prob,
    const int* __restrict__ bidx, int L)
{
    int i = blockIdx.x * blockDim.x + threadIdx.x;
    if (i >= L) return;
    float gx = clipf(__ldg(&pos[3 * i + 0])) * 64.0f;
    float gy = clipf(__ldg(&pos[3 * i + 1])) * 64.0f;
    float gz = clipf(__ldg(&pos[3 * i + 2])) * 64.0f;
    int bx = (int)gx, by = (int)gy;
    int b  = __ldg(&bidx[i]) & 7;
    unsigned bin  = (unsigned)((b << 12) | (bx << 6) | by);
    unsigned slot = atomicAdd(&g_cursor[bin], 1u);
    g_sval[slot] = make_float4(gx, gy, gz, __ldg(&prob[i]));
}

// ---------------------------------------------------------------------------
// P2G: one warp per output column. Lanes deposit particles (warp-uniform
// rounds, coalesced loads) into lane-private smem column copies (no atomics,
// no bank conflicts), then 32-way conflict-free reduce + fused divide + store.
// ---------------------------------------------------------------------------
__global__ void __launch_bounds__(64) p2g_kernel(float* __restrict__ out) {
    __shared__ __align__(16) float acc[2][32 * ACC_STRIDE];
    int warp = threadIdx.x >> 5;
    int lane = threadIdx.x & 31;
    int col  = blockIdx.x * 2 + warp;          // (b<<12)|(x<<6)|y
    int b = col >> 12, x = (col >> 6) & 63, y = col & 63;

    float* wa = acc[warp];

    // zero this warp's 32 copies (float4 stores)
    {
        float4* a4 = reinterpret_cast<float4*>(wa);
        const int n4 = (32 * ACC_STRIDE) / 4;  // 1112
        #pragma unroll
        for (int k = 0; k < (n4 + 31) / 32; k++) {
            int idx = lane + k * 32;
            if (idx < n4) a4[idx] = make_float4(0.f, 0.f, 0.f, 0.f);
        }
        // tail floats (32*139 = 4448 = 1112*4 exactly -> no tail)
    }
    __syncwarp();

    float* mycopy = wa + lane * ACC_STRIDE;

    #pragma unroll
    for (int dxn = -1; dxn <= 1; dxn++) {
        int nx = x + dxn;
        if ((unsigned)nx >= 64u) continue;     // warp-uniform
        #pragma unroll
        for (int dyn = -1; dyn <= 1; dyn++) {
            int ny = y + dyn;
            if ((unsigned)ny >= 64u) continue; // warp-uniform
            int bin = (b << 12) | (nx << 6) | ny;
            unsigned s0 = __ldg(&g_start[bin]);
            unsigned s1 = __ldg(&g_start[bin + 1]);
            for (unsigned j0 = s0; j0 < s1; j0 += 32) {   // warp-uniform count
                unsigned j = j0 + lane;
                if (j < s1) {
                    float4 p = g_sval[j];
                    float fx = p.x - floorf(p.x);
                    float fy = p.y - floorf(p.y);
                    float bzf = floorf(p.z);
                    float fz = p.z - bzf;
                    int   bz = (int)bzf;

                    float m  = wsel(dxn, fx) * wsel(dyn, fy);
                    float mp = m * p.w;

                    float t0 = 1.0f - fz;
                    float wz0 = 0.5f * t0 * t0;            // tap z-1
                    float t1 = fz - 0.5f;
                    float wz1 = 0.75f - t1 * t1;           // tap z
                    float wz2 = 0.5f * fz * fz;            // tap z+1

                    float* d = mycopy + 2 * bz;            // zi = bz+t -> off 2bz+2t+v
                    d[0] += m  * wz0;  d[1] += mp * wz0;
                    d[2] += m  * wz1;  d[3] += mp * wz1;
                    d[4] += m  * wz2;  d[5] += mp * wz2;
                }
            }
        }
    }
    __syncwarp();

    // reduce 32 copies -> 132 sums (o-major, bank-conflict-free)
    float sums[5];
    #pragma unroll
    for (int k = 0; k < 5; k++) {
        int o = lane + k * 32;
        float s = 0.0f;
        if (o < ACC_USED) {
            #pragma unroll
            for (int c = 0; c < 32; c++)
                s += wa[c * ACC_STRIDE + o];
        }
        sums[k] = s;
    }
    __syncwarp();
    #pragma unroll
    for (int k = 0; k < 5; k++) {
        int o = lane + k * 32;
        if (o < ACC_USED) wa[o] = sums[k];
    }
    __syncwarp();

    // flush: cell z reads zi = z+1 (zi 0 and 65 are dropped out-of-box taps)
    float* obase = out + (size_t)col * 64;
    #pragma unroll
    for (int h = 0; h < 2; h++) {
        int z = lane + h * 32;
        float w  = wa[2 * (z + 1)];
        float wp = wa[2 * (z + 1) + 1];
        obase[z] = wp / (w + EPS_DIV);
    }
}

// ---------------------------------------------------------------------------
extern "C" void kernel_launch(void* const* d_in, const int* in_sizes, int n_in,
                              void* d_out, int out_size)
{
    const float* pos  = (const float*)d_in[0];
    const float* prob = (const float*)d_in[1];
    const int*   bidx = (const int*)d_in[2];
    int L = in_sizes[1];

    int pblocks = (L + 255) / 256;

    zero_hist_kernel<<<(NBINS + 1023) / 1024, 1024>>>();
    hist_kernel<<<pblocks, 256>>>(pos, bidx, L);
    scan1_kernel<<<128, 256>>>();
    scan2_kernel<<<1, 128>>>();
    scan3_kernel<<<128, 256>>>();
    reorder_kernel<<<pblocks, 256>>>(pos, prob, bidx, L);
    p2g_kernel<<<NBINS / 2, 64>>>((float*)d_out);
}

// round 16
// speedup vs baseline: 1.0898x; 1.0448x over previous
#include <cuda_runtime.h>
#include <cstdint>

#define GRID_N   64
#define BMAX     8
#define NBINS    (BMAX * GRID_N * GRID_N)   // 32768 column bins (b,x,y)
#define LMAX     (1 << 20)
#define EPS_CLIP 1e-5f
#define EPS_DIV  1e-7f
#define NSLOT    132                        // zi in [0,65] x {w, wp}

__device__ __align__(16) float4  g_sval[LMAX];     // sorted {xg, yg, zg, prob}
__device__ unsigned              g_hist[NBINS];
__device__ unsigned              g_cursor[NBINS];
__device__ unsigned              g_start[NBINS + 1];
__device__ unsigned              g_bsum[128];
__device__ unsigned              g_boff[128];

__device__ __forceinline__ float clipf(float v) {
    return fminf(fmaxf(v, EPS_CLIP), 1.0f - EPS_CLIP);
}

// ---------------------------------------------------------------------------
__global__ void zero_hist_kernel() {
    int i = blockIdx.x * blockDim.x + threadIdx.x;
    if (i < NBINS) g_hist[i] = 0u;
}

// ---------------------------------------------------------------------------
__global__ void __launch_bounds__(256) hist_kernel(
    const float* __restrict__ pos, const int* __restrict__ bidx, int L)
{
    int i = blockIdx.x * blockDim.x + threadIdx.x;
    if (i >= L) return;
    int bx = (int)(clipf(__ldg(&pos[3 * i + 0])) * 64.0f);
    int by = (int)(clipf(__ldg(&pos[3 * i + 1])) * 64.0f);
    int b  = __ldg(&bidx[i]) & 7;
    atomicAdd(&g_hist[(b << 12) | (bx << 6) | by], 1u);
}

// ---------------------------------------------------------------------------
// exclusive scan of 32K bins: per-block scan, warp scan of 128 block sums, add
// ---------------------------------------------------------------------------
__global__ void __launch_bounds__(256) scan1_kernel() {   // 128 blocks x 256
    __shared__ unsigned s[256];
    int t = threadIdx.x;
    int gid = blockIdx.x * 256 + t;
    unsigned v = g_hist[gid];
    s[t] = v;
    __syncthreads();
    for (int d = 1; d < 256; d <<= 1) {
        unsigned u = (t >= d) ? s[t - d] : 0u;
        __syncthreads();
        s[t] += u;
        __syncthreads();
    }
    g_cursor[gid] = s[t] - v;
    if (t == 255) g_bsum[blockIdx.x] = s[t];
}

__global__ void scan2_kernel() {                          // 1 block x 32
    int l = threadIdx.x;
    unsigned carry = 0;
    #pragma unroll
    for (int seg = 0; seg < 4; seg++) {
        unsigned v = g_bsum[seg * 32 + l];
        unsigned inc = v;
        #pragma unroll
        for (int d = 1; d < 32; d <<= 1) {
            unsigned u = __shfl_up_sync(0xffffffffu, inc, d);
            if (l >= d) inc += u;
        }
        g_boff[seg * 32 + l] = carry + inc - v;           // exclusive
        carry += __shfl_sync(0xffffffffu, inc, 31);
    }
    if (l == 0) g_start[NBINS] = carry;                   // total = L
}

__global__ void __launch_bounds__(256) scan3_kernel() {   // 128 blocks x 256
    int gid = blockIdx.x * 256 + threadIdx.x;
    unsigned v = g_cursor[gid] + g_boff[blockIdx.x];
    g_cursor[gid] = v;
    g_start[gid]  = v;
}

// ---------------------------------------------------------------------------
// reorder particles into column-bin-sorted order
// ---------------------------------------------------------------------------
__global__ void __launch_bounds__(512) reorder_kernel(
    const float* __restrict__ pos, const float* __restrict__ prob,
    const int* __restrict__ bidx, int L)
{
    int i = blockIdx.x * blockDim.x + threadIdx.x;
    if (i >= L) return;
    float gx = clipf(__ldg(&pos[3 * i + 0])) * 64.0f;
    float gy = clipf(__ldg(&pos[3 * i + 1])) * 64.0f;
    float gz = clipf(__ldg(&pos[3 * i + 2])) * 64.0f;
    int bx = (int)gx, by = (int)gy;
    int b  = __ldg(&bidx[i]) & 7;
    unsigned bin  = (unsigned)((b << 12) | (bx << 6) | by);
    unsigned slot = atomicAdd(&g_cursor[bin], 1u);
    g_sval[slot] = make_float4(gx, gy, gz, __ldg(&prob[i]));
}

// ---------------------------------------------------------------------------
// P2G gather: one warp per output column. Accumulator layout [slot][lane]
// -> bank = lane for ANY per-lane slot: deposits are conflict-free.
// Diagonal reduce is conflict-free. No atomics anywhere.
// ---------------------------------------------------------------------------
__global__ void __launch_bounds__(64) p2g_kernel(float* __restrict__ out) {
    __shared__ __align__(16) float acc[2][NSLOT][32];     // 33,792 B
    int warp = threadIdx.x >> 5;
    int lane = threadIdx.x & 31;
    int col  = blockIdx.x * 2 + warp;                     // (b<<12)|(x<<6)|y
    int b = col >> 12, x = (col >> 6) & 63, y = col & 63;

    float (*wa)[32] = acc[warp];

    // zero: 132*32 floats = 1056 float4, row-major, conflict-free
    {
        float4* a4 = reinterpret_cast<float4*>(&wa[0][0]);
        const float4 z4 = make_float4(0.f, 0.f, 0.f, 0.f);
        #pragma unroll
        for (int k = 0; k < 33; k++) a4[lane + k * 32] = z4;
    }
    __syncwarp();

    float* base = &wa[0][lane];      // slot s lives at base[s*32], bank = lane

    #pragma unroll
    for (int dxn = -1; dxn <= 1; dxn++) {
        int nx = x + dxn;
        if ((unsigned)nx >= 64u) continue;                // warp-uniform
        #pragma unroll
        for (int dyn = -1; dyn <= 1; dyn++) {
            int ny = y + dyn;
            if ((unsigned)ny >= 64u) continue;            // warp-uniform
            int bin = (b << 12) | (nx << 6) | ny;
            unsigned s0 = __ldg(&g_start[bin]);
            unsigned s1 = __ldg(&g_start[bin + 1]);
            for (unsigned j0 = s0; j0 < s1; j0 += 32) {   // warp-uniform trips
                unsigned j = j0 + lane;
                if (j < s1) {
                    float4 p = g_sval[j];
                    int ix = (int)p.x, iy = (int)p.y, iz = (int)p.z;
                    float fx = p.x - (float)ix;
                    float fy = p.y - (float)iy;
                    float fz = p.z - (float)iz;

                    // weight of this particle on column (x,y): tap = -dxn/-dyn
                    float wxv, wyv;
                    if      (dxn < 0) wxv = 0.5f * fx * fx;
                    else if (dxn > 0) { float t = 1.0f - fx; wxv = 0.5f * t * t; }
                    else              { float t = fx - 0.5f; wxv = 0.75f - t * t; }
                    if      (dyn < 0) wyv = 0.5f * fy * fy;
                    else if (dyn > 0) { float t = 1.0f - fy; wyv = 0.5f * t * t; }
                    else              { float t = fy - 0.5f; wyv = 0.75f - t * t; }

                    float m  = wxv * wyv;
                    float mp = m * p.w;

                    float t0 = 1.0f - fz;
                    float wz0 = 0.5f * t0 * t0;           // tap z-1 -> zi = iz
                    float t1 = fz - 0.5f;
                    float wz1 = 0.75f - t1 * t1;          // tap z   -> zi = iz+1
                    float wz2 = 0.5f * fz * fz;           // tap z+1 -> zi = iz+2

                    int s = 2 * iz * 32;                  // slot offset in floats
                    base[s        ] += m  * wz0;
                    base[s +   32 ] += mp * wz0;
                    base[s + 2*32 ] += m  * wz1;
                    base[s + 3*32 ] += mp * wz1;
                    base[s + 4*32 ] += m  * wz2;
                    base[s + 5*32 ] += mp * wz2;
                }
            }
        }
    }
    __syncwarp();

    // diagonal reduce: slot s = lane + 32k, read copies c at (lane+c)&31
    float sums[5];
    #pragma unroll
    for (int k = 0; k < 5; k++) {
        int s = lane + 32 * k;
        float a = 0.0f;
        if (s < NSLOT) {
            #pragma unroll
            for (int c = 0; c < 32; c++)
                a += wa[s][(lane + c) & 31];
        }
        sums[k] = a;
    }
    __syncwarp();
    float* flat = &wa[0][0];
    #pragma unroll
    for (int k = 0; k < 5; k++) {
        int s = lane + 32 * k;
        if (s < NSLOT) flat[s] = sums[k];                 // bank = lane
    }
    __syncwarp();

    // flush: cell z reads zi = z+1 (zi 0 and 65 are dropped out-of-box taps)
    const float2* fp = reinterpret_cast<const float2*>(flat);
    float* obase = out + (size_t)col * 64;
    #pragma unroll
    for (int h = 0; h < 2; h++) {
        int z = lane + 32 * h;
        float2 v = fp[z + 1];                             // {w, wp}
        obase[z] = v.y / (v.x + EPS_DIV);
    }
}

// ---------------------------------------------------------------------------
extern "C" void kernel_launch(void* const* d_in, const int* in_sizes, int n_in,
                              void* d_out, int out_size)
{
    const float* pos  = (const float*)d_in[0];
    const float* prob = (const float*)d_in[1];
    const int*   bidx = (const int*)d_in[2];
    int L = in_sizes[1];

    zero_hist_kernel<<<(NBINS + 1023) / 1024, 1024>>>();
    hist_kernel<<<(L + 255) / 256, 256>>>(pos, bidx, L);
    scan1_kernel<<<128, 256>>>();
    scan2_kernel<<<1, 32>>>();
    scan3_kernel<<<128, 256>>>();
    reorder_kernel<<<(L + 511) / 512, 512>>>(pos, prob, bidx, L);
    p2g_kernel<<<NBINS / 2, 64>>>((float*)d_out);
}